// round 12
// baseline (speedup 1.0000x reference)
#include <cuda_runtime.h>

#define Nn 16
#define Wt 256
#define Tt 2048
#define DIMc 256
#define TILE_T 32
#define PSTRIDE 36   // floats; 144B row: 16B-aligned groups, broadcast-only reads

// ---------------- scratch (static device globals) ----------------
__device__ __align__(16) float d_cr[Nn * Wt * 16];   // per-(n,w) folded layer1 bias (score branch)
__device__ __align__(8)  float d_cl[Nn * Wt * 2];    // per-(n,w) folded layer1 bias (C branch)
__device__ float d_start[Nn * Wt];
__device__ float d_end[Nn * Wt];
__device__ float d_P[Nn * Tt * Wt];                  // normalized softmax weights, layout (n, t, w)
__device__ float d_ctx[Nn * Tt * 2];                 // (ctx0, ctx1) per (n, t)

// ---------------- f32x2 packed helpers ----------------
typedef unsigned long long u64;

__device__ __forceinline__ u64 pk2(float lo, float hi) {
    u64 r; asm("mov.b64 %0,{%1,%2};" : "=l"(r) : "f"(lo), "f"(hi)); return r;
}
__device__ __forceinline__ void upk2(u64 v, float& lo, float& hi) {
    asm("mov.b64 {%0,%1},%2;" : "=f"(lo), "=f"(hi) : "l"(v));
}
__device__ __forceinline__ u64 fma2(u64 a, u64 b, u64 c) {
    u64 d; asm("fma.rn.f32x2 %0,%1,%2,%3;" : "=l"(d) : "l"(a), "l"(b), "l"(c)); return d;
}
__device__ __forceinline__ u64 mul2(u64 a, u64 b) {
    u64 d; asm("mul.rn.f32x2 %0,%1,%2;" : "=l"(d) : "l"(a), "l"(b)); return d;
}

// exact silu (used in prep path only)
__device__ __forceinline__ float silu_f(float x) {
    return __fdividef(x, 1.0f + __expf(-x));
}

// fast silu via hardware tanh: silu(x) = 0.5x + 0.5x*tanh(0.5x)   (1 MUFU)
__device__ __forceinline__ float tanh_ap(float x) {
    float y; asm("tanh.approx.f32 %0,%1;" : "=f"(y) : "f"(x)); return y;
}
__device__ __forceinline__ float silu_t(float x) {
    float xh = 0.5f * x;
    return fmaf(xh, tanh_ap(xh), xh);
}
__device__ __forceinline__ u64 silu2_t(u64 x2) {
    u64 xh2 = mul2(x2, pk2(0.5f, 0.5f));
    float lo, hi; upk2(xh2, lo, hi);
    u64 th2 = pk2(tanh_ap(lo), tanh_ap(hi));
    return fma2(xh2, th2, xh2);
}

// ---------------- kernel 1: inclusive cumsum of durations per batch ----------------
__global__ void scan_kernel(const float* __restrict__ dur) {
    int n = blockIdx.x;
    int w = threadIdx.x;
    __shared__ float s[Wt];
    float v = dur[n * Wt + w];
    s[w] = v;
    __syncthreads();
    #pragma unroll
    for (int off = 1; off < Wt; off <<= 1) {
        float add = (w >= off) ? s[w - off] : 0.0f;
        __syncthreads();
        s[w] += add;
        __syncthreads();
    }
    float en = s[w];
    d_end[n * Wt + w] = en;
    d_start[n * Wt + w] = en - v;
}

// ---------------- kernel 2: conv1d(k=3)+BN+SiLU both branches, fold into c_r/c_l ----------------
__global__ void prep_kernel(const float* __restrict__ features,
                            const float* __restrict__ c1w, const float* __restrict__ c1b,
                            const float* __restrict__ g1, const float* __restrict__ b1,
                            const float* __restrict__ m1, const float* __restrict__ v1,
                            const float* __restrict__ c2w, const float* __restrict__ c2b,
                            const float* __restrict__ g2, const float* __restrict__ b2,
                            const float* __restrict__ m2, const float* __restrict__ v2,
                            const float* __restrict__ sb1w1, const float* __restrict__ sb1b1,
                            const float* __restrict__ sb2w1, const float* __restrict__ sb2b1) {
    int nw = blockIdx.x;
    int n = nw / Wt, w = nw % Wt;
    int i = threadIdx.x;

    float p1[8], p2[8];
    #pragma unroll
    for (int o = 0; o < 8; o++) { p1[o] = 0.f; p2[o] = 0.f; }

    #pragma unroll
    for (int h = 0; h < 3; h++) {
        int ww = w + h - 1;
        if (ww < 0 || ww >= Wt) continue;
        float xv = features[(n * Wt + ww) * DIMc + i];
        #pragma unroll
        for (int o = 0; o < 8; o++) {
            p1[o] = fmaf(xv, __ldg(c1w + o * 768 + i * 3 + h), p1[o]);
            p2[o] = fmaf(xv, __ldg(c2w + o * 768 + i * 3 + h), p2[o]);
        }
    }

    __shared__ float red[16][257];
    #pragma unroll
    for (int o = 0; o < 8; o++) { red[o][i] = p1[o]; red[8 + o][i] = p2[o]; }
    __syncthreads();
    for (int s = 128; s > 0; s >>= 1) {
        if (i < s) {
            #pragma unroll
            for (int o = 0; o < 16; o++) red[o][i] += red[o][i + s];
        }
        __syncthreads();
    }

    if (i == 0) {
        float left[8], right[8];
        #pragma unroll
        for (int o = 0; o < 8; o++) {
            float y1 = red[o][0] + c1b[o];
            y1 = (y1 - m1[o]) * rsqrtf(v1[o] + 1e-5f) * g1[o] + b1[o];
            left[o] = silu_f(y1);
            float y2 = red[8 + o][0] + c2b[o];
            y2 = (y2 - m2[o]) * rsqrtf(v2[o] + 1e-5f) * g2[o] + b2[o];
            right[o] = silu_f(y2);
        }
        float st = d_start[nw], en = d_end[nw];
        #pragma unroll
        for (int j = 0; j < 16; j++) {
            float c = sb2b1[j] - st * sb2w1[j] + en * sb2w1[16 + j];
            #pragma unroll
            for (int o = 0; o < 8; o++) c = fmaf(right[o], sb2w1[(2 + o) * 16 + j], c);
            d_cr[nw * 16 + j] = c;
        }
        #pragma unroll
        for (int j = 0; j < 2; j++) {
            float c = sb1b1[j] - st * sb1w1[j] + en * sb1w1[2 + j];
            #pragma unroll
            for (int o = 0; o < 8; o++) c = fmaf(left[o], sb1w1[(2 + o) * 2 + j], c);
            d_cl[nw * 2 + j] = c;
        }
    }
}

// ---------------- kernel 3: MLPs, 4 t per thread processed SEQUENTIALLY (low regs,
// natural occupancy) + fused softmax + ctx. No min-blocks cap -> no spill risk. ----------------
#define TB 4   // t's per block / per thread
__global__ void __launch_bounds__(256) score_kernel(
    const float* __restrict__ Tarr,
    const float* __restrict__ sb2w1, const float* __restrict__ sb2w2, const float* __restrict__ sb2b2,
    const float* __restrict__ p2w, const float* __restrict__ p2b,
    const float* __restrict__ sb1w1, const float* __restrict__ sb1w2, const float* __restrict__ sb1b2) {
    int t0 = blockIdx.x * TB, n = blockIdx.y;
    int w = threadIdx.x, lane = w & 31, warp = w >> 5;

    __shared__ __align__(16) float W2t[16][16];   // W2t[j2][j] = sb2w2[j][j2]
    __shared__ __align__(16) float a_rs[16];
    __shared__ float b2s[16], p2s[16];
    __shared__ float a_ls[2], V2s[4], vb2s[2], pbias_s[1];
    __shared__ float rbuf[16][8];

    {
        int j2 = w >> 4, j = w & 15;
        W2t[j2][j] = sb2w2[j * 16 + j2];
        if (w < 16) {
            a_rs[w] = sb2w1[w] - sb2w1[16 + w];
            b2s[w] = sb2b2[w];
            p2s[w] = p2w[w];
        }
        if (w < 2) {
            a_ls[w] = sb1w1[w] - sb1w1[2 + w];
            vb2s[w] = sb1b2[w];
            V2s[w] = sb1w2[w];         // V2[0][w]
            V2s[2 + w] = sb1w2[2 + w]; // V2[1][w]
        }
        if (w == 0) pbias_s[0] = p2b[0];
    }
    __syncthreads();

    int nw = n * Wt + w;

    float4 cv[4];
    {
        const float4* crp = reinterpret_cast<const float4*>(d_cr + nw * 16);
        #pragma unroll
        for (int q = 0; q < 4; q++) cv[q] = __ldg(crp + q);
    }
    float2 cl = *reinterpret_cast<const float2*>(d_cl + nw * 2);

    float sc[TB], C0[TB], C1[TB];

    #pragma unroll
    for (int k = 0; k < TB; k++) {
        float tf = __ldg(Tarr + t0 + k);
        u64 tf2 = pk2(tf, tf);

        // layer1 for this t: h2[8] packed pairs of silu(t*a + c)
        u64 h2[8];
        {
            const float4* ap = reinterpret_cast<const float4*>(a_rs);
            #pragma unroll
            for (int q = 0; q < 4; q++) {
                float4 av = ap[q];
                u64 c0 = pk2(cv[q].x, cv[q].y), c1 = pk2(cv[q].z, cv[q].w);
                u64 a0 = pk2(av.x, av.y), a1 = pk2(av.z, av.w);
                h2[2 * q + 0] = silu2_t(fma2(tf2, a0, c0));
                h2[2 * q + 1] = silu2_t(fma2(tf2, a1, c1));
            }
        }

        // layer2 + proj2 (16 independent j2 chains -> ILP within one t)
        float s = pbias_s[0];
        #pragma unroll
        for (int j2 = 0; j2 < 16; j2++) {
            const ulonglong2* wp = reinterpret_cast<const ulonglong2*>(W2t[j2]);
            ulonglong2 w01 = wp[0], w23 = wp[1], w45 = wp[2], w67 = wp[3];
            u64 acc = pk2(b2s[j2], 0.0f);
            acc = fma2(h2[0], w01.x, acc);
            acc = fma2(h2[1], w01.y, acc);
            acc = fma2(h2[2], w23.x, acc);
            acc = fma2(h2[3], w23.y, acc);
            acc = fma2(h2[4], w45.x, acc);
            acc = fma2(h2[5], w45.y, acc);
            acc = fma2(h2[6], w67.x, acc);
            acc = fma2(h2[7], w67.y, acc);
            float lo, hi; upk2(acc, lo, hi);
            s = fmaf(silu_t(lo + hi), p2s[j2], s);
        }
        sc[k] = s;

        // C branch for this t
        float g0 = silu_t(fmaf(tf, a_ls[0], cl.x));
        float g1 = silu_t(fmaf(tf, a_ls[1], cl.y));
        C0[k] = silu_t(fmaf(g0, V2s[0], fmaf(g1, V2s[2], vb2s[0])));
        C1[k] = silu_t(fmaf(g0, V2s[1], fmaf(g1, V2s[3], vb2s[1])));
    }

    // ---- fused softmax over the 256 w in this block, for each of the TB t's ----
    #pragma unroll
    for (int k = 0; k < TB; k++) {
        float m = sc[k];
        #pragma unroll
        for (int o = 16; o; o >>= 1) m = fmaxf(m, __shfl_xor_sync(0xffffffffu, m, o));
        if (lane == 0) rbuf[12 + k][warp] = m;
    }
    __syncthreads();
    float e[TB];
    #pragma unroll
    for (int k = 0; k < TB; k++) {
        float m = rbuf[12 + k][0];
        #pragma unroll
        for (int i = 1; i < 8; i++) m = fmaxf(m, rbuf[12 + k][i]);
        e[k] = __expf(sc[k] - m);
    }
    #pragma unroll
    for (int k = 0; k < TB; k++) {
        float a = e[k], b = e[k] * C0[k], c = e[k] * C1[k];
        #pragma unroll
        for (int o = 16; o; o >>= 1) {
            a += __shfl_xor_sync(0xffffffffu, a, o);
            b += __shfl_xor_sync(0xffffffffu, b, o);
            c += __shfl_xor_sync(0xffffffffu, c, o);
        }
        if (lane == 0) { rbuf[k][warp] = a; rbuf[4 + k][warp] = b; rbuf[8 + k][warp] = c; }
    }
    __syncthreads();
    #pragma unroll
    for (int k = 0; k < TB; k++) {
        float sa = 0.f, sb = 0.f, s2 = 0.f;
        #pragma unroll
        for (int i = 0; i < 8; i++) { sa += rbuf[k][i]; sb += rbuf[4 + k][i]; s2 += rbuf[8 + k][i]; }
        float inv = __fdividef(1.0f, sa);
        d_P[((size_t)(n * Tt) + t0 + k) * Wt + w] = e[k] * inv;
        if (w == k) {
            d_ctx[(n * Tt + t0 + k) * 2 + 0] = sb * inv;
            d_ctx[(n * Tt + t0 + k) * 2 + 1] = s2 * inv;
        }
    }
}

// ---------------- kernel 4: out = P @ features + ctx @ proj1 + b ----------------
// grid (1024, 2): x = (n, t-tile), y = d-half. block = 256 threads =
// 4 t-groups (8 rows each) x 64 d-threads (2 cols each) -> low regs, high occ.
__global__ void __launch_bounds__(256, 5) out_kernel(const float* __restrict__ features,
                                                     const float* __restrict__ proj1w,
                                                     const float* __restrict__ proj1b,
                                                     float* __restrict__ out) {
    __shared__ __align__(16) float Ps[Wt * PSTRIDE];   // transposed: Ps[w*PSTRIDE + r]
    __shared__ float ctx0[TILE_T], ctx1[TILE_T];

    int blk = blockIdx.x;
    int n = blk >> 6;                    // Tt/TILE_T = 64 tiles per n
    int t0 = (blk & 63) * TILE_T;
    int tid = threadIdx.x;

    // phase 1: stage normalized P (transposed) + ctx
    const float* Pg = d_P + ((size_t)n * Tt + t0) * Wt;
    #pragma unroll
    for (int r = 0; r < TILE_T; r++) Ps[tid * PSTRIDE + r] = Pg[r * Wt + tid];
    if (tid < TILE_T) {
        float2 c = *reinterpret_cast<const float2*>(d_ctx + (n * Tt + t0 + tid) * 2);
        ctx0[tid] = c.x; ctx1[tid] = c.y;
    }
    __syncthreads();

    int tg = tid >> 6;                   // t-group 0..3 -> rows [tg*8, tg*8+8)
    int dt = tid & 63;
    int d = blockIdx.y * 128 + dt * 2;   // 2 consecutive d per thread

    u64 acc[4][2];                       // [r-pair 0..3][d 0..1]
    #pragma unroll
    for (int rp = 0; rp < 4; rp++) {
        acc[rp][0] = 0ULL; acc[rp][1] = 0ULL;
    }

    const float2* fp = reinterpret_cast<const float2*>(features + (size_t)n * Wt * DIMc + d);
    const char* psb = reinterpret_cast<const char*>(Ps + tg * 8);

    #pragma unroll 8
    for (int w = 0; w < Wt; w++) {
        float2 f = __ldg(fp + w * (DIMc / 2));
        u64 fd0 = pk2(f.x, f.x), fd1 = pk2(f.y, f.y);
        const ulonglong2* pr = reinterpret_cast<const ulonglong2*>(psb + (size_t)w * (PSTRIDE * 4));
        ulonglong2 p01 = pr[0];   // (r0,r1),(r2,r3)
        ulonglong2 p23 = pr[1];   // (r4,r5),(r6,r7)
        acc[0][0] = fma2(p01.x, fd0, acc[0][0]);
        acc[0][1] = fma2(p01.x, fd1, acc[0][1]);
        acc[1][0] = fma2(p01.y, fd0, acc[1][0]);
        acc[1][1] = fma2(p01.y, fd1, acc[1][1]);
        acc[2][0] = fma2(p23.x, fd0, acc[2][0]);
        acc[2][1] = fma2(p23.x, fd1, acc[2][1]);
        acc[3][0] = fma2(p23.y, fd0, acc[3][0]);
        acc[3][1] = fma2(p23.y, fd1, acc[3][1]);
    }

    float2 pw0 = *reinterpret_cast<const float2*>(proj1w + d);
    float2 pw1 = *reinterpret_cast<const float2*>(proj1w + DIMc + d);
    float2 pbv = *reinterpret_cast<const float2*>(proj1b + d);
    float* op = out + ((size_t)(n * Tt + t0)) * DIMc + d;

    #pragma unroll
    for (int rp = 0; rp < 4; rp++) {
        float lo0, hi0, lo1, hi1;
        upk2(acc[rp][0], lo0, hi0);
        upk2(acc[rp][1], lo1, hi1);
        int r0 = tg * 8 + 2 * rp;
        float c0a = ctx0[r0], c1a = ctx1[r0];
        float c0b = ctx0[r0 + 1], c1b = ctx1[r0 + 1];
        float2 oA, oB;
        oA.x = fmaf(c0a, pw0.x, fmaf(c1a, pw1.x, lo0 + pbv.x));
        oA.y = fmaf(c0a, pw0.y, fmaf(c1a, pw1.y, lo1 + pbv.y));
        oB.x = fmaf(c0b, pw0.x, fmaf(c1b, pw1.x, hi0 + pbv.x));
        oB.y = fmaf(c0b, pw0.y, fmaf(c1b, pw1.y, hi1 + pbv.y));
        *reinterpret_cast<float2*>(op + (size_t)r0 * DIMc) = oA;
        *reinterpret_cast<float2*>(op + (size_t)(r0 + 1) * DIMc) = oB;
    }
}

// ---------------- launch ----------------
extern "C" void kernel_launch(void* const* d_in, const int* in_sizes, int n_in,
                              void* d_out, int out_size) {
    const float* T_arr    = (const float*)d_in[0];
    const float* durations= (const float*)d_in[1];
    const float* features = (const float*)d_in[2];
    const float* conv1_w  = (const float*)d_in[3];
    const float* conv1_b  = (const float*)d_in[4];
    const float* bn1_g    = (const float*)d_in[5];
    const float* bn1_b    = (const float*)d_in[6];
    const float* bn1_m    = (const float*)d_in[7];
    const float* bn1_v    = (const float*)d_in[8];
    const float* conv2_w  = (const float*)d_in[9];
    const float* conv2_b  = (const float*)d_in[10];
    const float* bn2_g    = (const float*)d_in[11];
    const float* bn2_b    = (const float*)d_in[12];
    const float* bn2_m    = (const float*)d_in[13];
    const float* bn2_v    = (const float*)d_in[14];
    const float* sb1_w1   = (const float*)d_in[15];
    const float* sb1_b1   = (const float*)d_in[16];
    const float* sb1_w2   = (const float*)d_in[17];
    const float* sb1_b2   = (const float*)d_in[18];
    const float* sb2_w1   = (const float*)d_in[19];
    const float* sb2_b1   = (const float*)d_in[20];
    const float* sb2_w2   = (const float*)d_in[21];
    const float* sb2_b2   = (const float*)d_in[22];
    const float* proj1_w  = (const float*)d_in[23];
    const float* proj1_b  = (const float*)d_in[24];
    const float* proj2_w  = (const float*)d_in[25];
    const float* proj2_b  = (const float*)d_in[26];
    float* out = (float*)d_out;

    scan_kernel<<<Nn, Wt>>>(durations);
    prep_kernel<<<Nn * Wt, DIMc>>>(features, conv1_w, conv1_b, bn1_g, bn1_b, bn1_m, bn1_v,
                                   conv2_w, conv2_b, bn2_g, bn2_b, bn2_m, bn2_v,
                                   sb1_w1, sb1_b1, sb2_w1, sb2_b1);
    dim3 sg(Tt / TB, Nn);
    score_kernel<<<sg, Wt>>>(T_arr, sb2_w1, sb2_w2, sb2_b2, proj2_w, proj2_b,
                             sb1_w1, sb1_w2, sb1_b2);
    dim3 og(Nn * (Tt / TILE_T), 2);
    out_kernel<<<og, 256>>>(features, proj1_w, proj1_b, out);
}

// round 14
// speedup vs baseline: 2.1376x; 2.1376x over previous
#include <cuda_runtime.h>

#define Nn 16
#define Wt 256
#define Tt 2048
#define DIMc 256
#define TILE_T 32
#define PSTRIDE 36   // floats; 144B row: 16B-aligned groups, broadcast-only reads

// ---------------- scratch (static device globals) ----------------
__device__ __align__(16) float d_cr[Nn * Wt * 16];   // per-(n,w) folded layer1 bias (score branch)
__device__ __align__(8)  float d_cl[Nn * Wt * 2];    // per-(n,w) folded layer1 bias (C branch)
__device__ float d_start[Nn * Wt];
__device__ float d_end[Nn * Wt];
__device__ float d_P[Nn * Tt * Wt];                  // normalized softmax weights, layout (n, t, w)
__device__ float d_ctx[Nn * Tt * 2];                 // (ctx0, ctx1) per (n, t)

// ---------------- f32x2 packed helpers ----------------
typedef unsigned long long u64;

__device__ __forceinline__ u64 pk2(float lo, float hi) {
    u64 r; asm("mov.b64 %0,{%1,%2};" : "=l"(r) : "f"(lo), "f"(hi)); return r;
}
__device__ __forceinline__ void upk2(u64 v, float& lo, float& hi) {
    asm("mov.b64 {%0,%1},%2;" : "=f"(lo), "=f"(hi) : "l"(v));
}
__device__ __forceinline__ u64 fma2(u64 a, u64 b, u64 c) {
    u64 d; asm("fma.rn.f32x2 %0,%1,%2,%3;" : "=l"(d) : "l"(a), "l"(b), "l"(c)); return d;
}
__device__ __forceinline__ u64 mul2(u64 a, u64 b) {
    u64 d; asm("mul.rn.f32x2 %0,%1,%2;" : "=l"(d) : "l"(a), "l"(b)); return d;
}

// exact silu (used in prep path only)
__device__ __forceinline__ float silu_f(float x) {
    return __fdividef(x, 1.0f + __expf(-x));
}

// fast silu via hardware tanh: silu(x) = 0.5x + 0.5x*tanh(0.5x)   (1 MUFU)
__device__ __forceinline__ float tanh_ap(float x) {
    float y; asm("tanh.approx.f32 %0,%1;" : "=f"(y) : "f"(x)); return y;
}
__device__ __forceinline__ float silu_t(float x) {
    float xh = 0.5f * x;
    return fmaf(xh, tanh_ap(xh), xh);
}
__device__ __forceinline__ u64 silu2_t(u64 x2) {
    u64 xh2 = mul2(x2, pk2(0.5f, 0.5f));
    float lo, hi; upk2(xh2, lo, hi);
    u64 th2 = pk2(tanh_ap(lo), tanh_ap(hi));
    return fma2(xh2, th2, xh2);
}

// ---------------- kernel 1: inclusive cumsum of durations per batch ----------------
__global__ void scan_kernel(const float* __restrict__ dur) {
    int n = blockIdx.x;
    int w = threadIdx.x;
    __shared__ float s[Wt];
    float v = dur[n * Wt + w];
    s[w] = v;
    __syncthreads();
    #pragma unroll
    for (int off = 1; off < Wt; off <<= 1) {
        float add = (w >= off) ? s[w - off] : 0.0f;
        __syncthreads();
        s[w] += add;
        __syncthreads();
    }
    float en = s[w];
    d_end[n * Wt + w] = en;
    d_start[n * Wt + w] = en - v;
}

// ---------------- kernel 2: conv1d(k=3)+BN+SiLU both branches, fold into c_r/c_l ----------------
__global__ void prep_kernel(const float* __restrict__ features,
                            const float* __restrict__ c1w, const float* __restrict__ c1b,
                            const float* __restrict__ g1, const float* __restrict__ b1,
                            const float* __restrict__ m1, const float* __restrict__ v1,
                            const float* __restrict__ c2w, const float* __restrict__ c2b,
                            const float* __restrict__ g2, const float* __restrict__ b2,
                            const float* __restrict__ m2, const float* __restrict__ v2,
                            const float* __restrict__ sb1w1, const float* __restrict__ sb1b1,
                            const float* __restrict__ sb2w1, const float* __restrict__ sb2b1) {
    int nw = blockIdx.x;
    int n = nw / Wt, w = nw % Wt;
    int i = threadIdx.x;
    int lane = i & 31, warp = i >> 5;

    float p1[8], p2[8];
    #pragma unroll
    for (int o = 0; o < 8; o++) { p1[o] = 0.f; p2[o] = 0.f; }

    #pragma unroll
    for (int h = 0; h < 3; h++) {
        int ww = w + h - 1;
        if (ww < 0 || ww >= Wt) continue;
        float xv = features[(n * Wt + ww) * DIMc + i];
        #pragma unroll
        for (int o = 0; o < 8; o++) {
            p1[o] = fmaf(xv, __ldg(c1w + o * 768 + i * 3 + h), p1[o]);
            p2[o] = fmaf(xv, __ldg(c2w + o * 768 + i * 3 + h), p2[o]);
        }
    }

    // warp-level shfl reduction, then 8 partials per channel
    #pragma unroll
    for (int o = 0; o < 8; o++) {
        #pragma unroll
        for (int off = 16; off; off >>= 1) {
            p1[o] += __shfl_xor_sync(0xffffffffu, p1[o], off);
            p2[o] += __shfl_xor_sync(0xffffffffu, p2[o], off);
        }
    }
    __shared__ float part[16][8];
    if (lane == 0) {
        #pragma unroll
        for (int o = 0; o < 8; o++) { part[o][warp] = p1[o]; part[8 + o][warp] = p2[o]; }
    }
    __syncthreads();

    if (i == 0) {
        float left[8], right[8];
        #pragma unroll
        for (int o = 0; o < 8; o++) {
            float s1 = 0.f, s2 = 0.f;
            #pragma unroll
            for (int q = 0; q < 8; q++) { s1 += part[o][q]; s2 += part[8 + o][q]; }
            float y1 = s1 + c1b[o];
            y1 = (y1 - m1[o]) * rsqrtf(v1[o] + 1e-5f) * g1[o] + b1[o];
            left[o] = silu_f(y1);
            float y2 = s2 + c2b[o];
            y2 = (y2 - m2[o]) * rsqrtf(v2[o] + 1e-5f) * g2[o] + b2[o];
            right[o] = silu_f(y2);
        }
        float st = d_start[nw], en = d_end[nw];
        #pragma unroll
        for (int j = 0; j < 16; j++) {
            float c = sb2b1[j] - st * sb2w1[j] + en * sb2w1[16 + j];
            #pragma unroll
            for (int o = 0; o < 8; o++) c = fmaf(right[o], sb2w1[(2 + o) * 16 + j], c);
            d_cr[nw * 16 + j] = c;
        }
        #pragma unroll
        for (int j = 0; j < 2; j++) {
            float c = sb1b1[j] - st * sb1w1[j] + en * sb1w1[2 + j];
            #pragma unroll
            for (int o = 0; o < 8; o++) c = fmaf(left[o], sb1w1[(2 + o) * 2 + j], c);
            d_cl[nw * 2 + j] = c;
        }
    }
}

// ---------------- kernel 3: MLPs for 4 t per thread + fused softmax + ctx ----------------
// (R3-measured configuration: launch_bounds(256,2), interleaved h2[TB][8], loads after barrier)
#define TB 4   // t's per block / per thread
__global__ void __launch_bounds__(256, 2) score_kernel(
    const float* __restrict__ Tarr,
    const float* __restrict__ sb2w1, const float* __restrict__ sb2w2, const float* __restrict__ sb2b2,
    const float* __restrict__ p2w, const float* __restrict__ p2b,
    const float* __restrict__ sb1w1, const float* __restrict__ sb1w2, const float* __restrict__ sb1b2) {
    int t0 = blockIdx.x * TB, n = blockIdx.y;
    int w = threadIdx.x, lane = w & 31, warp = w >> 5;

    __shared__ __align__(16) float W2t[16][16];   // W2t[j2][j] = sb2w2[j][j2]
    __shared__ __align__(16) float a_rs[16];
    __shared__ float b2s[16], p2s[16];
    __shared__ float a_ls[2], V2s[4], vb2s[2], pbias_s[1];
    __shared__ float rbuf[16][8];

    {
        int j2 = w >> 4, j = w & 15;
        W2t[j2][j] = sb2w2[j * 16 + j2];
        if (w < 16) {
            a_rs[w] = sb2w1[w] - sb2w1[16 + w];
            b2s[w] = sb2b2[w];
            p2s[w] = p2w[w];
        }
        if (w < 2) {
            a_ls[w] = sb1w1[w] - sb1w1[2 + w];
            vb2s[w] = sb1b2[w];
            V2s[w] = sb1w2[w];         // V2[0][w]
            V2s[2 + w] = sb1w2[2 + w]; // V2[1][w]
        }
        if (w == 0) pbias_s[0] = p2b[0];
    }
    __syncthreads();

    int nw = n * Wt + w;

    float tf[TB];
    u64 tf2[TB];
    #pragma unroll
    for (int k = 0; k < TB; k++) { tf[k] = __ldg(Tarr + t0 + k); tf2[k] = pk2(tf[k], tf[k]); }

    // layer1: h2[k][jp] packed pairs of silu(t*a + c)
    u64 h2[TB][8];
    {
        const float4* crp = reinterpret_cast<const float4*>(d_cr + nw * 16);
        const float4* ap = reinterpret_cast<const float4*>(a_rs);
        #pragma unroll
        for (int q = 0; q < 4; q++) {
            float4 cv = __ldg(crp + q);
            float4 av = ap[q];
            u64 c0 = pk2(cv.x, cv.y), c1 = pk2(cv.z, cv.w);
            u64 a0 = pk2(av.x, av.y), a1 = pk2(av.z, av.w);
            #pragma unroll
            for (int k = 0; k < TB; k++) {
                h2[k][2 * q + 0] = silu2_t(fma2(tf2[k], a0, c0));
                h2[k][2 * q + 1] = silu2_t(fma2(tf2[k], a1, c1));
            }
        }
    }

    // layer2 + proj2: score[k]
    float sc[TB];
    #pragma unroll
    for (int k = 0; k < TB; k++) sc[k] = pbias_s[0];
    #pragma unroll
    for (int j2 = 0; j2 < 16; j2++) {
        const ulonglong2* wp = reinterpret_cast<const ulonglong2*>(W2t[j2]);
        ulonglong2 w01 = wp[0], w23 = wp[1], w45 = wp[2], w67 = wp[3];
        float bj = b2s[j2], pj = p2s[j2];
        u64 binit = pk2(bj, 0.0f);
        u64 acc[TB];
        #pragma unroll
        for (int k = 0; k < TB; k++) acc[k] = binit;
        #pragma unroll
        for (int k = 0; k < TB; k++) {
            acc[k] = fma2(h2[k][0], w01.x, acc[k]);
            acc[k] = fma2(h2[k][1], w01.y, acc[k]);
            acc[k] = fma2(h2[k][2], w23.x, acc[k]);
            acc[k] = fma2(h2[k][3], w23.y, acc[k]);
            acc[k] = fma2(h2[k][4], w45.x, acc[k]);
            acc[k] = fma2(h2[k][5], w45.y, acc[k]);
            acc[k] = fma2(h2[k][6], w67.x, acc[k]);
            acc[k] = fma2(h2[k][7], w67.y, acc[k]);
        }
        #pragma unroll
        for (int k = 0; k < TB; k++) {
            float lo, hi; upk2(acc[k], lo, hi);
            sc[k] = fmaf(silu_t(lo + hi), pj, sc[k]);
        }
    }

    // C branch
    float C0[TB], C1[TB];
    {
        float2 cl = *reinterpret_cast<const float2*>(d_cl + nw * 2);
        float al0 = a_ls[0], al1 = a_ls[1];
        float v00 = V2s[0], v01 = V2s[1], v10 = V2s[2], v11 = V2s[3];
        float vb0 = vb2s[0], vb1 = vb2s[1];
        #pragma unroll
        for (int k = 0; k < TB; k++) {
            float g0 = silu_t(fmaf(tf[k], al0, cl.x));
            float g1 = silu_t(fmaf(tf[k], al1, cl.y));
            C0[k] = silu_t(fmaf(g0, v00, fmaf(g1, v10, vb0)));
            C1[k] = silu_t(fmaf(g0, v01, fmaf(g1, v11, vb1)));
        }
    }

    // ---- fused softmax over the 256 w in this block, for each of the TB t's ----
    #pragma unroll
    for (int k = 0; k < TB; k++) {
        float m = sc[k];
        #pragma unroll
        for (int o = 16; o; o >>= 1) m = fmaxf(m, __shfl_xor_sync(0xffffffffu, m, o));
        if (lane == 0) rbuf[12 + k][warp] = m;
    }
    __syncthreads();
    float e[TB];
    #pragma unroll
    for (int k = 0; k < TB; k++) {
        float m = rbuf[12 + k][0];
        #pragma unroll
        for (int i = 1; i < 8; i++) m = fmaxf(m, rbuf[12 + k][i]);
        e[k] = __expf(sc[k] - m);
    }
    #pragma unroll
    for (int k = 0; k < TB; k++) {
        float a = e[k], b = e[k] * C0[k], c = e[k] * C1[k];
        #pragma unroll
        for (int o = 16; o; o >>= 1) {
            a += __shfl_xor_sync(0xffffffffu, a, o);
            b += __shfl_xor_sync(0xffffffffu, b, o);
            c += __shfl_xor_sync(0xffffffffu, c, o);
        }
        if (lane == 0) { rbuf[k][warp] = a; rbuf[4 + k][warp] = b; rbuf[8 + k][warp] = c; }
    }
    __syncthreads();
    #pragma unroll
    for (int k = 0; k < TB; k++) {
        float sa = 0.f, sb = 0.f, s2 = 0.f;
        #pragma unroll
        for (int i = 0; i < 8; i++) { sa += rbuf[k][i]; sb += rbuf[4 + k][i]; s2 += rbuf[8 + k][i]; }
        float inv = __fdividef(1.0f, sa);
        d_P[((size_t)(n * Tt) + t0 + k) * Wt + w] = e[k] * inv;
        if (w == k) {
            d_ctx[(n * Tt + t0 + k) * 2 + 0] = sb * inv;
            d_ctx[(n * Tt + t0 + k) * 2 + 1] = s2 * inv;
        }
    }
}

// ---------------- kernel 4: out = P @ features + ctx @ proj1 + b ----------------
// grid (1024, 2): x = (n, t-tile), y = d-half. block = 128 threads =
// 4 t-groups (8 rows each) x 32 d-threads (4 cols each).
// Fewer L1 wavefronts per fma2: per 16 fma2 = 1 LDG.128 (4wf) + 2 LDS.128 (2wf).
__global__ void __launch_bounds__(128) out_kernel(const float* __restrict__ features,
                                                  const float* __restrict__ proj1w,
                                                  const float* __restrict__ proj1b,
                                                  float* __restrict__ out) {
    __shared__ __align__(16) float Ps[Wt * PSTRIDE];   // transposed: Ps[w*PSTRIDE + r]
    __shared__ float ctx0[TILE_T], ctx1[TILE_T];

    int blk = blockIdx.x;
    int n = blk >> 6;                    // Tt/TILE_T = 64 tiles per n
    int t0 = (blk & 63) * TILE_T;
    int tid = threadIdx.x;

    // phase 1: stage normalized P (transposed) + ctx
    const float* Pg = d_P + ((size_t)n * Tt + t0) * Wt;
    #pragma unroll
    for (int wc = 0; wc < 2; wc++) {
        int wcol = tid + wc * 128;
        #pragma unroll
        for (int r = 0; r < TILE_T; r++) Ps[wcol * PSTRIDE + r] = Pg[r * Wt + wcol];
    }
    if (tid < TILE_T) {
        float2 c = *reinterpret_cast<const float2*>(d_ctx + (n * Tt + t0 + tid) * 2);
        ctx0[tid] = c.x; ctx1[tid] = c.y;
    }
    __syncthreads();

    int tg = tid >> 5;                   // t-group 0..3 -> rows [tg*8, tg*8+8)
    int dt = tid & 31;
    int d = blockIdx.y * 128 + dt * 4;   // 4 consecutive d per thread

    u64 acc[4][4];                       // [r-pair 0..3][d 0..3]
    #pragma unroll
    for (int rp = 0; rp < 4; rp++)
        #pragma unroll
        for (int dj = 0; dj < 4; dj++) acc[rp][dj] = 0ULL;

    const float4* fp = reinterpret_cast<const float4*>(features + (size_t)n * Wt * DIMc + d);
    const char* psb = reinterpret_cast<const char*>(Ps + tg * 8);

    #pragma unroll 4
    for (int w = 0; w < Wt; w++) {
        float4 f = __ldg(fp + w * (DIMc / 4));
        u64 fd0 = pk2(f.x, f.x), fd1 = pk2(f.y, f.y);
        u64 fd2 = pk2(f.z, f.z), fd3 = pk2(f.w, f.w);
        const ulonglong2* pr = reinterpret_cast<const ulonglong2*>(psb + (size_t)w * (PSTRIDE * 4));
        ulonglong2 p01 = pr[0];   // (r0,r1),(r2,r3)
        ulonglong2 p23 = pr[1];   // (r4,r5),(r6,r7)
        acc[0][0] = fma2(p01.x, fd0, acc[0][0]);
        acc[0][1] = fma2(p01.x, fd1, acc[0][1]);
        acc[0][2] = fma2(p01.x, fd2, acc[0][2]);
        acc[0][3] = fma2(p01.x, fd3, acc[0][3]);
        acc[1][0] = fma2(p01.y, fd0, acc[1][0]);
        acc[1][1] = fma2(p01.y, fd1, acc[1][1]);
        acc[1][2] = fma2(p01.y, fd2, acc[1][2]);
        acc[1][3] = fma2(p01.y, fd3, acc[1][3]);
        acc[2][0] = fma2(p23.x, fd0, acc[2][0]);
        acc[2][1] = fma2(p23.x, fd1, acc[2][1]);
        acc[2][2] = fma2(p23.x, fd2, acc[2][2]);
        acc[2][3] = fma2(p23.x, fd3, acc[2][3]);
        acc[3][0] = fma2(p23.y, fd0, acc[3][0]);
        acc[3][1] = fma2(p23.y, fd1, acc[3][1]);
        acc[3][2] = fma2(p23.y, fd2, acc[3][2]);
        acc[3][3] = fma2(p23.y, fd3, acc[3][3]);
    }

    float4 pw0 = *reinterpret_cast<const float4*>(proj1w + d);
    float4 pw1 = *reinterpret_cast<const float4*>(proj1w + DIMc + d);
    float4 pbv = *reinterpret_cast<const float4*>(proj1b + d);
    float* op = out + ((size_t)(n * Tt + t0)) * DIMc + d;

    #pragma unroll
    for (int rp = 0; rp < 4; rp++) {
        float lo[4], hi[4];
        #pragma unroll
        for (int dj = 0; dj < 4; dj++) upk2(acc[rp][dj], lo[dj], hi[dj]);
        int r0 = tg * 8 + 2 * rp;
        float c0a = ctx0[r0], c1a = ctx1[r0];
        float c0b = ctx0[r0 + 1], c1b = ctx1[r0 + 1];
        float4 oA, oB;
        oA.x = fmaf(c0a, pw0.x, fmaf(c1a, pw1.x, lo[0] + pbv.x));
        oA.y = fmaf(c0a, pw0.y, fmaf(c1a, pw1.y, lo[1] + pbv.y));
        oA.z = fmaf(c0a, pw0.z, fmaf(c1a, pw1.z, lo[2] + pbv.z));
        oA.w = fmaf(c0a, pw0.w, fmaf(c1a, pw1.w, lo[3] + pbv.w));
        oB.x = fmaf(c0b, pw0.x, fmaf(c1b, pw1.x, hi[0] + pbv.x));
        oB.y = fmaf(c0b, pw0.y, fmaf(c1b, pw1.y, hi[1] + pbv.y));
        oB.z = fmaf(c0b, pw0.z, fmaf(c1b, pw1.z, hi[2] + pbv.z));
        oB.w = fmaf(c0b, pw0.w, fmaf(c1b, pw1.w, hi[3] + pbv.w));
        *reinterpret_cast<float4*>(op + (size_t)r0 * DIMc) = oA;
        *reinterpret_cast<float4*>(op + (size_t)(r0 + 1) * DIMc) = oB;
    }
}

// ---------------- launch ----------------
extern "C" void kernel_launch(void* const* d_in, const int* in_sizes, int n_in,
                              void* d_out, int out_size) {
    const float* T_arr    = (const float*)d_in[0];
    const float* durations= (const float*)d_in[1];
    const float* features = (const float*)d_in[2];
    const float* conv1_w  = (const float*)d_in[3];
    const float* conv1_b  = (const float*)d_in[4];
    const float* bn1_g    = (const float*)d_in[5];
    const float* bn1_b    = (const float*)d_in[6];
    const float* bn1_m    = (const float*)d_in[7];
    const float* bn1_v    = (const float*)d_in[8];
    const float* conv2_w  = (const float*)d_in[9];
    const float* conv2_b  = (const float*)d_in[10];
    const float* bn2_g    = (const float*)d_in[11];
    const float* bn2_b    = (const float*)d_in[12];
    const float* bn2_m    = (const float*)d_in[13];
    const float* bn2_v    = (const float*)d_in[14];
    const float* sb1_w1   = (const float*)d_in[15];
    const float* sb1_b1   = (const float*)d_in[16];
    const float* sb1_w2   = (const float*)d_in[17];
    const float* sb1_b2   = (const float*)d_in[18];
    const float* sb2_w1   = (const float*)d_in[19];
    const float* sb2_b1   = (const float*)d_in[20];
    const float* sb2_w2   = (const float*)d_in[21];
    const float* sb2_b2   = (const float*)d_in[22];
    const float* proj1_w  = (const float*)d_in[23];
    const float* proj1_b  = (const float*)d_in[24];
    const float* proj2_w  = (const float*)d_in[25];
    const float* proj2_b  = (const float*)d_in[26];
    float* out = (float*)d_out;

    scan_kernel<<<Nn, Wt>>>(durations);
    prep_kernel<<<Nn * Wt, DIMc>>>(features, conv1_w, conv1_b, bn1_g, bn1_b, bn1_m, bn1_v,
                                   conv2_w, conv2_b, bn2_g, bn2_b, bn2_m, bn2_v,
                                   sb1_w1, sb1_b1, sb2_w1, sb2_b1);
    dim3 sg(Tt / TB, Nn);
    score_kernel<<<sg, Wt>>>(T_arr, sb2_w1, sb2_w2, sb2_b2, proj2_w, proj2_b,
                             sb1_w1, sb1_w2, sb1_b2);
    dim3 og(Nn * (Tt / TILE_T), 2);
    out_kernel<<<og, 128>>>(features, proj1_w, proj1_b, out);
}